// round 11
// baseline (speedup 1.0000x reference)
#include <cuda_runtime.h>
#include <cuda_bf16.h>
#include <math.h>
#include <stdint.h>

#define BB 8
#define CC 384
#define NN 1024
#define NH 8
#define HD 48
#define HID 192
#define NBIAS 3969
#define BIAS_STRIDE 4096
#define QK_SCALE 0.14433756729740643f  // 48^-0.5
#define NCHUNK 18          // K' = 1152 split dim / 64
#define MT_QKV 64
#define NT_QKV 9
#define MT_PROJ 3
#define NT_PROJ 64

// ---------------- PTX helpers ----------------------------------------------
__device__ __forceinline__ uint32_t cvta_smem(const void* p) {
    uint32_t a;
    asm("{ .reg .u64 t; cvta.to.shared.u64 t, %1; cvt.u32.u64 %0, t; }" : "=r"(a) : "l"(p));
    return a;
}
__device__ __forceinline__ void ldsm4(uint32_t &r0, uint32_t &r1, uint32_t &r2,
                                      uint32_t &r3, uint32_t addr) {
    asm volatile("ldmatrix.sync.aligned.m8n8.x4.shared.b16 {%0,%1,%2,%3}, [%4];"
                 : "=r"(r0), "=r"(r1), "=r"(r2), "=r"(r3) : "r"(addr));
}
__device__ __forceinline__ void ldsm4t(uint32_t &r0, uint32_t &r1, uint32_t &r2,
                                       uint32_t &r3, uint32_t addr) {
    asm volatile("ldmatrix.sync.aligned.m8n8.x4.trans.shared.b16 {%0,%1,%2,%3}, [%4];"
                 : "=r"(r0), "=r"(r1), "=r"(r2), "=r"(r3) : "r"(addr));
}
__device__ __forceinline__ void mma16816(float* c, uint32_t a0, uint32_t a1,
                                         uint32_t a2, uint32_t a3,
                                         uint32_t b0, uint32_t b1) {
    asm volatile(
        "mma.sync.aligned.m16n8k16.row.col.f32.bf16.bf16.f32 "
        "{%0,%1,%2,%3}, {%4,%5,%6,%7}, {%8,%9}, {%0,%1,%2,%3};"
        : "+f"(c[0]), "+f"(c[1]), "+f"(c[2]), "+f"(c[3])
        : "r"(a0), "r"(a1), "r"(a2), "r"(a3), "r"(b0), "r"(b1));
}
__device__ __forceinline__ void cp16(uint32_t dst, const void* src) {
    asm volatile("cp.async.cg.shared.global [%0], [%1], 16;" :: "r"(dst), "l"(src));
}
#define CP_COMMIT() asm volatile("cp.async.commit_group;")
#define CP_WAIT0()  asm volatile("cp.async.wait_group 0;")
#define CP_WAIT1()  asm volatile("cp.async.wait_group 1;")

// pack two f32 -> bf16x2 (lo in low half)
__device__ __forceinline__ uint32_t packbf2(float lo, float hi) {
    uint32_t r; asm("cvt.rn.bf16x2.f32 %0, %1, %2;" : "=r"(r) : "f"(hi), "f"(lo)); return r;
}
__device__ __forceinline__ float lo_as_f(uint32_t u) { return __uint_as_float(u << 16); }
__device__ __forceinline__ float hi_as_f(uint32_t u) { return __uint_as_float(u & 0xFFFF0000u); }

// ---------------- scratch globals (zero-init; no runtime alloc) -------------
__device__ float g_bias[NH * BIAS_STRIDE];
// split-bf16 swizzled tile images, [.. tile][split hi/lo][8192 bf16 = 16KB]
__device__ __nv_bfloat16 g_Qt[(size_t)BB*NH*8*2*8192];   // Q, pre-scaled
__device__ __nv_bfloat16 g_Kt[(size_t)BB*NH*8*2*8192];
__device__ __nv_bfloat16 g_Vt[(size_t)BB*NH*8*2*8192];
// GEMM operand images (chunk-major)
__device__ __nv_bfloat16 g_XA[(size_t)MT_QKV * NCHUNK * 8192];   // tokens (hi,hi,lo)
__device__ __nv_bfloat16 g_WQ[(size_t)NT_QKV * NCHUNK * 8192];   // qkv_w^T (hi,lo,hi)
__device__ __nv_bfloat16 g_AT[(size_t)NT_PROJ * NCHUNK * 8192];  // attn out (hi,hi,lo)
__device__ __nv_bfloat16 g_WP[(size_t)MT_PROJ * NCHUNK * 8192];  // proj_w^T (hi,lo,hi)

__device__ __forceinline__ unsigned sw128(unsigned off) {
    return off ^ ((off >> 3) & 0x70);
}
__device__ __forceinline__ uint4 pack8(const unsigned short* h) {
    uint4 u;
    u.x = h[0] | ((unsigned)h[1] << 16);
    u.y = h[2] | ((unsigned)h[3] << 16);
    u.z = h[4] | ((unsigned)h[5] << 16);
    u.w = h[6] | ((unsigned)h[7] << 16);
    return u;
}

// ---------------------------------------------------------------------------
// 1) Relative-bias MLP over the 63x63 unique relative offsets
// ---------------------------------------------------------------------------
__global__ void bias_kernel(const float* __restrict__ w1, const float* __restrict__ b1,
                            const float* __restrict__ w2, const float* __restrict__ b2) {
    int p = blockIdx.x * blockDim.x + threadIdx.x;
    if (p >= NBIAS) return;
    int dh = p / 63, dw = p % 63;
    float rh = (float)(dh - 31) * (1.0f / 31.0f);
    float rw = (float)(dw - 31) * (1.0f / 31.0f);
    float out[NH];
#pragma unroll
    for (int h = 0; h < NH; h++) out[h] = b2[h];
    for (int k = 0; k < HID; k++) {
        float pre = rh * w1[k] + rw * w1[HID + k] + b1[k];
        float g = 0.5f * pre * (1.0f + erff(pre * 0.70710678118654752f));
#pragma unroll
        for (int h = 0; h < NH; h++) out[h] += g * w2[k * NH + h];
    }
#pragma unroll
    for (int h = 0; h < NH; h++) g_bias[h * BIAS_STRIDE + p] = out[h];
}

// ---------------------------------------------------------------------------
// 2) Unified operand-conversion kernel
// ---------------------------------------------------------------------------
__global__ __launch_bounds__(256) void conv_all(const float* __restrict__ x,
                                                const float* __restrict__ qkv_w,
                                                const float* __restrict__ proj_w) {
    int blk = blockIdx.x;
    int role, tile, chunk;
    if (blk < NCHUNK * MT_QKV)            { role = 0; tile = blk / NCHUNK; chunk = blk % NCHUNK; }
    else if (blk < NCHUNK * (MT_QKV + NT_QKV)) {
        int t = blk - NCHUNK * MT_QKV;      role = 1; tile = t / NCHUNK; chunk = t % NCHUNK;
    } else {
        int t = blk - NCHUNK * (MT_QKV + NT_QKV); role = 2; tile = t / NCHUNK; chunk = t % NCHUNK;
    }
    const int term = chunk / 6;
    const int kbase = chunk * 64 - term * 384;

    if (role == 0) {
        const bool lo = (term == 2);
        __nv_bfloat16* dst = g_XA + ((size_t)(tile * NCHUNK + chunk)) * 8192;
        for (int idx = threadIdx.x; idx < 1024; idx += 256) {
            int r = idx & 127, g = idx >> 7;
            int token = tile * 128 + r;
            int b = token >> 10, n = token & 1023;
            const float* s = x + ((size_t)(b * CC + kbase + g * 8)) * NN + n;
            unsigned short hh[8];
#pragma unroll
            for (int j = 0; j < 8; j++) {
                float v = s[(size_t)j * NN];
                __nv_bfloat16 h = __float2bfloat16(v);
                if (lo) h = __float2bfloat16(v - __bfloat162float(h));
                hh[j] = __bfloat16_as_ushort(h);
            }
            *(uint4*)((char*)dst + sw128((unsigned)(r * 128 + g * 16))) = pack8(hh);
        }
    } else {
        const bool lo = (term == 1);
        const float* src = (role == 1) ? qkv_w : proj_w;
        const int ks = (role == 1) ? 3 * CC : CC;
        __nv_bfloat16* dst = ((role == 1) ? g_WQ : g_WP) +
                             ((size_t)(tile * NCHUNK + chunk)) * 8192;
        for (int idx = threadIdx.x; idx < 1024; idx += 256) {
            int r = idx & 127, g = idx >> 7;
            int row = tile * 128 + r;
            const float* s = src + row + (size_t)(kbase + g * 8) * ks;
            unsigned short hh[8];
#pragma unroll
            for (int j = 0; j < 8; j++) {
                float v = s[(size_t)j * ks];
                __nv_bfloat16 h = __float2bfloat16(v);
                if (lo) h = __float2bfloat16(v - __bfloat162float(h));
                hh[j] = __bfloat16_as_ushort(h);
            }
            *(uint4*)((char*)dst + sw128((unsigned)(r * 128 + g * 16))) = pack8(hh);
        }
    }
}

// ---------------------------------------------------------------------------
// 3) cp.async double-buffered mma.sync GEMM mainloop (proven R10)
// ---------------------------------------------------------------------------
__device__ __forceinline__ void mma_mainloop_pipe(const uint4* __restrict__ At,
                                                  const uint4* __restrict__ Bt,
                                                  uint32_t sBase,
                                                  int tid, int warp_m, int warp_n,
                                                  float acc[4][4][4]) {
    const int lane = tid & 31;
    const int lrow = lane & 7;
    const int lmat = lane >> 3;
    const int rA0 = warp_m * 64 + ((lmat & 1) << 3) + lrow;
    const int rB0 = warp_n * 32 + ((lmat & 1) << 3) + lrow;
    const int gHalf = lmat >> 1;

    auto issue = [&](int c, int buf) {
        const uint4* Ac = At + c * 1024;
        const uint4* Bc = Bt + c * 1024;
        uint32_t base = sBase + buf * 32768;
#pragma unroll
        for (int i = tid; i < 1024; i += 256) cp16(base + i * 16, Ac + i);
#pragma unroll
        for (int i = tid; i < 1024; i += 256) cp16(base + 16384 + i * 16, Bc + i);
        CP_COMMIT();
    };

    issue(0, 0);
    for (int c = 0; c < NCHUNK; c++) {
        if (c + 1 < NCHUNK) { issue(c + 1, (c + 1) & 1); CP_WAIT1(); }
        else                { CP_WAIT0(); }
        __syncthreads();
        const uint32_t sA = sBase + (c & 1) * 32768;
        const uint32_t sB = sA + 16384;
#pragma unroll
        for (int ks = 0; ks < 4; ks++) {
            const int g = ks * 2 + gHalf;
            uint32_t a[4][4];
#pragma unroll
            for (int mt = 0; mt < 4; mt++) {
                int row = rA0 + mt * 16;
                uint32_t addr = sA + row * 128 + ((g ^ (row & 7)) << 4);
                ldsm4(a[mt][0], a[mt][1], a[mt][2], a[mt][3], addr);
            }
            uint32_t b[4][2];
#pragma unroll
            for (int np = 0; np < 2; np++) {
                int row = rB0 + np * 16;
                uint32_t addr = sB + row * 128 + ((g ^ (row & 7)) << 4);
                uint32_t r0, r1, r2, r3;
                ldsm4(r0, r1, r2, r3, addr);
                b[2*np][0] = r0; b[2*np][1] = r2;
                b[2*np+1][0] = r1; b[2*np+1][1] = r3;
            }
#pragma unroll
            for (int mt = 0; mt < 4; mt++)
#pragma unroll
                for (int nt = 0; nt < 4; nt++)
                    mma16816(acc[mt][nt], a[mt][0], a[mt][1], a[mt][2], a[mt][3],
                             b[nt][0], b[nt][1]);
        }
        __syncthreads();
    }
}

// qkv GEMM: epilogue writes split-bf16 swizzled Q/K/V tile images.
__global__ __launch_bounds__(256) void gemm_qkv_mma(const float* __restrict__ bias) {
    __shared__ __align__(16) uint4 sbuf[4096];     // 64 KB ping-pong
    const int nTile = blockIdx.x, mTile = blockIdx.y;
    const int tid = threadIdx.x, lane = tid & 31, wid = tid >> 5;
    const int warp_m = wid & 1, warp_n = wid >> 1;

    float acc[4][4][4] = {};
    mma_mainloop_pipe(((const uint4*)g_XA) + (size_t)mTile * NCHUNK * 1024,
                      ((const uint4*)g_WQ) + (size_t)nTile * NCHUNK * 1024,
                      cvta_smem(sbuf), tid, warp_m, warp_n, acc);

    const int which = (nTile * 128) / CC;
    __nv_bfloat16* dst = (which == 0) ? g_Qt : (which == 1 ? g_Kt : g_Vt);
    const float scale = (which == 0) ? QK_SCALE : 1.0f;
    const int rbase = mTile * 128 + warp_m * 64 + (lane >> 2);
    const int cbase = nTile * 128 + warp_n * 32 + (lane & 3) * 2;
#pragma unroll
    for (int nt = 0; nt < 4; nt++) {
        int col = cbase + nt * 8;
        int c = col - which * CC;
        int head = c / HD, d = c - head * HD;
        float2 bb = *(const float2*)&bias[col];
#pragma unroll
        for (int mt = 0; mt < 4; mt++)
#pragma unroll
            for (int half = 0; half < 2; half++) {
                int token = rbase + mt * 16 + half * 8;
                int b = token >> 10, n = token & 1023;
                float vx = (acc[mt][nt][half*2+0] + bb.x) * scale;
                float vy = (acc[mt][nt][half*2+1] + bb.y) * scale;
                uint32_t hp = packbf2(vx, vy);
                uint32_t lp = packbf2(vx - lo_as_f(hp), vy - hi_as_f(hp));
                size_t img = ((size_t)((b * NH + head) * 8 + (n >> 7))) * 2;
                int row = n & 127;
                unsigned off = (unsigned)(row * 128) +
                               ((((unsigned)d >> 3) ^ (row & 7)) << 4) + (d & 7) * 2;
                *(uint32_t*)((char*)(dst + img * 8192) + off) = hp;
                *(uint32_t*)((char*)(dst + (img + 1) * 8192) + off) = lp;
            }
    }
}

// proj GEMM: out[b][c][n]
__global__ __launch_bounds__(256) void gemm_proj_mma(const float* __restrict__ pb,
                                                     float* __restrict__ out) {
    __shared__ __align__(16) uint4 sbuf[4096];
    const int nTile = blockIdx.x, mTile = blockIdx.y;
    const int tid = threadIdx.x, lane = tid & 31, wid = tid >> 5;
    const int warp_m = wid & 1, warp_n = wid >> 1;

    float acc[4][4][4] = {};
    mma_mainloop_pipe(((const uint4*)g_WP) + (size_t)mTile * NCHUNK * 1024,
                      ((const uint4*)g_AT) + (size_t)nTile * NCHUNK * 1024,
                      cvta_smem(sbuf), tid, warp_m, warp_n, acc);

    const int b = (nTile * 128) >> 10;
    const int crow0 = mTile * 128 + warp_m * 64 + (lane >> 2);
    const int tok0  = nTile * 128 + warp_n * 32 + (lane & 3) * 2;
#pragma unroll
    for (int mt = 0; mt < 4; mt++)
#pragma unroll
        for (int half = 0; half < 2; half++) {
            int crow = crow0 + mt * 16 + half * 8;
            float pbv = pb[crow];
            float* orow = out + ((size_t)(b * CC + crow)) * NN;
#pragma unroll
            for (int nt = 0; nt < 4; nt++) {
                int token = tok0 + nt * 8;
                float2 v;
                v.x = acc[mt][nt][half*2+0] + pbv;
                v.y = acc[mt][nt][half*2+1] + pbv;
                *(float2*)(orow + (token & 1023)) = v;
            }
        }
}

// ---------------------------------------------------------------------------
// 4) Tensor-core flash attention, ILP-restructured MMA ordering.
// ---------------------------------------------------------------------------
#define ATTN_SMEM (16384 + 32768 + 2 * 65536)

__global__ __launch_bounds__(256) void attn_mma() {
    extern __shared__ char smem[];
    const int qt = blockIdx.x, h = blockIdx.y, b = blockIdx.z;
    const int tid = threadIdx.x, lane = tid & 31, warp = tid >> 5;
    const uint32_t sb = cvta_smem(smem);
    const uint32_t sQ = sb + 16384, sKV = sb + 49152;
    float* sBiasF = (float*)smem;

    const size_t bh = (size_t)(b * NH + h);

    {
        const char* gB = (const char*)(g_bias + h * BIAS_STRIDE);
        for (int i = tid; i < 1024; i += 256) cp16(sb + i * 16, gB + i * 16);
        const char* gQ = (const char*)(g_Qt + (bh * 8 + qt) * 2 * 8192);
        for (int i = tid; i < 2048; i += 256) cp16(sQ + i * 16, gQ + i * 16);
        const char* gK = (const char*)(g_Kt + (bh * 8 + 0) * 2 * 8192);
        const char* gV = (const char*)(g_Vt + (bh * 8 + 0) * 2 * 8192);
        for (int i = tid; i < 2048; i += 256) cp16(sKV + i * 16, gK + i * 16);
        for (int i = tid; i < 2048; i += 256) cp16(sKV + 32768 + i * 16, gV + i * 16);
        CP_COMMIT();
        CP_WAIT0();
        __syncthreads();
    }

    const int lrow = lane & 7, lmat = lane >> 3, gH = lmat >> 1;
    const int rowA = warp * 16 + ((lmat & 1) << 3) + lrow;
    uint32_t aQh[3][4], aQl[3][4];
#pragma unroll
    for (int ks = 0; ks < 3; ks++) {
        int g = 2 * ks + gH;
        uint32_t addr = sQ + rowA * 128 + ((g ^ (rowA & 7)) << 4);
        ldsm4(aQh[ks][0], aQh[ks][1], aQh[ks][2], aQh[ks][3], addr);
        ldsm4(aQl[ks][0], aQl[ks][1], aQl[ks][2], aQl[ks][3], addr + 16384);
    }

    const int q0 = qt * 128 + warp * 16 + (lane >> 2);
    const int q1 = q0 + 8;
    const int ih0 = q0 >> 5, iw0 = q0 & 31;
    const int ih1 = q1 >> 5, iw1 = q1 & 31;

    float Oacc[6][4] = {};
    float m0 = -1e30f, m1 = -1e30f, l0 = 0.0f, l1 = 0.0f;

    for (int kt = 0; kt < 8; kt++) {
        const uint32_t bufc = sKV + (kt & 1) * 65536;
        if (kt < 7) {
            const uint32_t bufn = sKV + ((kt + 1) & 1) * 65536;
            const char* gK = (const char*)(g_Kt + (bh * 8 + kt + 1) * 2 * 8192);
            const char* gV = (const char*)(g_Vt + (bh * 8 + kt + 1) * 2 * 8192);
            for (int i = tid; i < 2048; i += 256) cp16(bufn + i * 16, gK + i * 16);
            for (int i = tid; i < 2048; i += 256) cp16(bufn + 32768 + i * 16, gV + i * 16);
        }
        CP_COMMIT();

        // ---- S = Q K^T: kg processed in PAIRS -> 4 accumulator chains ----
        float S[16][4];
#pragma unroll
        for (int i = 0; i < 16; i++)
#pragma unroll
            for (int j = 0; j < 4; j++) S[i][j] = 0.0f;

#pragma unroll
        for (int kgp = 0; kgp < 4; kgp++) {
            const int rowB0 = kgp * 32 + ((lmat & 1) << 3) + lrow;
            const int rowB1 = rowB0 + 16;
            float* S0 = S[4*kgp + 0];
            float* S1 = S[4*kgp + 1];
            float* S2 = S[4*kgp + 2];
            float* S3 = S[4*kgp + 3];
#pragma unroll
            for (int ks = 0; ks < 3; ks++) {
                const int g = 2 * ks + gH;
                const uint32_t a0 = bufc + rowB0 * 128 + ((g ^ (rowB0 & 7)) << 4);
                const uint32_t a1 = bufc + rowB1 * 128 + ((g ^ (rowB1 & 7)) << 4);
                uint32_t h00,h01,h02,h03, h10,h11,h12,h13;
                uint32_t l00,l01,l02,l03, l10,l11,l12,l13;
                ldsm4(h00,h01,h02,h03, a0);            // Kh kg0
                ldsm4(h10,h11,h12,h13, a1);            // Kh kg1
                ldsm4(l00,l01,l02,l03, a0 + 16384);    // Kl kg0
                ldsm4(l10,l11,l12,l13, a1 + 16384);    // Kl kg1
                // 12 MMAs round-robin over 4 accumulators (distance-4 chains)
                mma16816(S0, aQh[ks][0],aQh[ks][1],aQh[ks][2],aQh[ks][3], h00,h02);
                mma16816(S1, aQh[ks][0],aQh[ks][1],aQh[ks][2],aQh[ks][3], h01,h03);
                mma16816(S2, aQh[ks][0],aQh[ks][1],aQh[ks][2],aQh[ks][3], h10,h12);
                mma16816(S3, aQh[ks][0],aQh[ks][1],aQh[ks][2],aQh[ks][3], h11,h13);
                mma16816(S0, aQl[ks][0],aQl[ks][1],aQl[ks][2],aQl[ks][3], h00,h02);
                mma16816(S1, aQl[ks][0],aQl[ks][1],aQl[ks][2],aQl[ks][3], h01,h03);
                mma16816(S2, aQl[ks][0],aQl[ks][1],aQl[ks][2],aQl[ks][3], h10,h12);
                mma16816(S3, aQl[ks][0],aQl[ks][1],aQl[ks][2],aQl[ks][3], h11,h13);
                mma16816(S0, aQh[ks][0],aQh[ks][1],aQh[ks][2],aQh[ks][3], l00,l02);
                mma16816(S1, aQh[ks][0],aQh[ks][1],aQh[ks][2],aQh[ks][3], l01,l03);
                mma16816(S2, aQh[ks][0],aQh[ks][1],aQh[ks][2],aQh[ks][3], l10,l12);
                mma16816(S3, aQh[ks][0],aQh[ks][1],aQh[ks][2],aQh[ks][3], l11,l13);
            }
        }

        // ---- bias + online softmax (unchanged) ----
        const int kb = kt * 128 + (lane & 3) * 2;
        float tm0 = -1e30f, tm1 = -1e30f;
#pragma unroll
        for (int nb = 0; nb < 16; nb++) {
            int k0 = kb + nb * 8, k1 = k0 + 1;
            int kh0 = k0 >> 5, kw0 = k0 & 31, kh1 = k1 >> 5, kw1 = k1 & 31;
            S[nb][0] += sBiasF[(ih0 - kh0 + 31) * 63 + (iw0 - kw0 + 31)];
            S[nb][1] += sBiasF[(ih0 - kh1 + 31) * 63 + (iw0 - kw1 + 31)];
            S[nb][2] += sBiasF[(ih1 - kh0 + 31) * 63 + (iw1 - kw0 + 31)];
            S[nb][3] += sBiasF[(ih1 - kh1 + 31) * 63 + (iw1 - kw1 + 31)];
            tm0 = fmaxf(tm0, fmaxf(S[nb][0], S[nb][1]));
            tm1 = fmaxf(tm1, fmaxf(S[nb][2], S[nb][3]));
        }
        tm0 = fmaxf(tm0, __shfl_xor_sync(0xFFFFFFFFu, tm0, 1));
        tm0 = fmaxf(tm0, __shfl_xor_sync(0xFFFFFFFFu, tm0, 2));
        tm1 = fmaxf(tm1, __shfl_xor_sync(0xFFFFFFFFu, tm1, 1));
        tm1 = fmaxf(tm1, __shfl_xor_sync(0xFFFFFFFFu, tm1, 2));
        float mn0 = fmaxf(m0, tm0), mn1 = fmaxf(m1, tm1);
        float al0 = __expf(m0 - mn0), al1 = __expf(m1 - mn1);
        m0 = mn0; m1 = mn1;
        l0 *= al0; l1 *= al1;
#pragma unroll
        for (int nb = 0; nb < 6; nb++) {
            Oacc[nb][0] *= al0; Oacc[nb][1] *= al0;
            Oacc[nb][2] *= al1; Oacc[nb][3] *= al1;
        }
        float ls0 = 0.0f, ls1 = 0.0f;
#pragma unroll
        for (int nb = 0; nb < 16; nb++) {
            S[nb][0] = __expf(S[nb][0] - m0); ls0 += S[nb][0];
            S[nb][1] = __expf(S[nb][1] - m0); ls0 += S[nb][1];
            S[nb][2] = __expf(S[nb][2] - m1); ls1 += S[nb][2];
            S[nb][3] = __expf(S[nb][3] - m1); ls1 += S[nb][3];
        }
        l0 += ls0; l1 += ls1;

        // ---- O += P V: all V frags loaded first, term-major MMA order ----
#pragma unroll
        for (int kg = 0; kg < 8; kg++) {
            uint32_t pa0 = packbf2(S[2*kg][0],   S[2*kg][1]);
            uint32_t pa1 = packbf2(S[2*kg][2],   S[2*kg][3]);
            uint32_t pa2 = packbf2(S[2*kg+1][0], S[2*kg+1][1]);
            uint32_t pa3 = packbf2(S[2*kg+1][2], S[2*kg+1][3]);
            uint32_t qa0 = packbf2(S[2*kg][0]   - lo_as_f(pa0), S[2*kg][1]   - hi_as_f(pa0));
            uint32_t qa1 = packbf2(S[2*kg][2]   - lo_as_f(pa1), S[2*kg][3]   - hi_as_f(pa1));
            uint32_t qa2 = packbf2(S[2*kg+1][0] - lo_as_f(pa2), S[2*kg+1][1] - hi_as_f(pa2));
            uint32_t qa3 = packbf2(S[2*kg+1][2] - lo_as_f(pa3), S[2*kg+1][3] - hi_as_f(pa3));
            const int rowV = kg * 16 + (lane & 15);
            uint32_t vh[3][4], vl[3][4];
#pragma unroll
            for (int dp = 0; dp < 3; dp++) {
                int g = dp * 2 + (lane >> 4);
                uint32_t addr = bufc + 32768 + rowV * 128 + ((g ^ (rowV & 7)) << 4);
                ldsm4t(vh[dp][0], vh[dp][1], vh[dp][2], vh[dp][3], addr);
                ldsm4t(vl[dp][0], vl[dp][1], vl[dp][2], vl[dp][3], addr + 16384);
            }
            // 18 MMAs term-major over 6 accumulators (distance-6 chains)
#pragma unroll
            for (int dp = 0; dp < 3; dp++) {
                mma16816(Oacc[2*dp],   pa0, pa1, pa2, pa3, vh[dp][0], vh[dp][1]);
                mma16816(Oacc[2*dp+1], pa0, pa1, pa2, pa3, vh[dp][2], vh[dp][3]);
            }
#pragma unroll
            for (int dp = 0; dp < 3; dp++) {
                mma16816(Oacc[2*dp],   qa0, qa1, qa2, qa3, vh[dp][0], vh[dp][1]);
                mma16816(Oacc[2*dp+1], qa0, qa1, qa2, qa3, vh[dp][2], vh[dp][3]);
            }
#pragma unroll
            for (int dp = 0; dp < 3; dp++) {
                mma16816(Oacc[2*dp],   pa0, pa1, pa2, pa3, vl[dp][0], vl[dp][1]);
                mma16816(Oacc[2*dp+1], pa0, pa1, pa2, pa3, vl[dp][2], vl[dp][3]);
            }
        }

        CP_WAIT0();
        __syncthreads();
    }

    l0 += __shfl_xor_sync(0xFFFFFFFFu, l0, 1);
    l0 += __shfl_xor_sync(0xFFFFFFFFu, l0, 2);
    l1 += __shfl_xor_sync(0xFFFFFFFFu, l1, 1);
    l1 += __shfl_xor_sync(0xFFFFFFFFu, l1, 2);
    const float inv0 = 1.0f / l0, inv1 = 1.0f / l1;

    const int token0 = b * NN + q0;
    const size_t tbase = (size_t)(token0 >> 7) * NCHUNK;
    const int row0 = token0 & 127;
#pragma unroll
    for (int nb = 0; nb < 6; nb++) {
        int d = nb * 8 + (lane & 3) * 2;
        int c = h * HD + d;
        int c6 = c >> 6;
        unsigned colc = (unsigned)(c & 63);
#pragma unroll
        for (int half = 0; half < 2; half++) {
            int row = row0 + half * 8;
            float vx = (half == 0 ? Oacc[nb][0] * inv0 : Oacc[nb][2] * inv1);
            float vy = (half == 0 ? Oacc[nb][1] * inv0 : Oacc[nb][3] * inv1);
            uint32_t hp = packbf2(vx, vy);
            uint32_t lp = packbf2(vx - lo_as_f(hp), vy - hi_as_f(hp));
            unsigned off = (unsigned)(row * 128) +
                           (((colc >> 3) ^ (row & 7)) << 4) + (colc & 7) * 2;
            *(uint32_t*)((char*)(g_AT + (tbase + c6) * 8192) + off) = hp;
            *(uint32_t*)((char*)(g_AT + (tbase + 6 + c6) * 8192) + off) = hp;
            *(uint32_t*)((char*)(g_AT + (tbase + 12 + c6) * 8192) + off) = lp;
        }
    }
}

// ---------------------------------------------------------------------------
extern "C" void kernel_launch(void* const* d_in, const int* in_sizes, int n_in,
                              void* d_out, int out_size) {
    const float* x      = (const float*)d_in[0];
    const float* qkv_w  = (const float*)d_in[1];
    const float* qkv_b  = (const float*)d_in[2];
    const float* proj_w = (const float*)d_in[3];
    const float* proj_b = (const float*)d_in[4];
    const float* mlp_w1 = (const float*)d_in[5];
    const float* mlp_b1 = (const float*)d_in[6];
    const float* mlp_w2 = (const float*)d_in[7];
    const float* mlp_b2 = (const float*)d_in[8];
    float* out = (float*)d_out;

    cudaFuncSetAttribute(attn_mma, cudaFuncAttributeMaxDynamicSharedMemorySize, ATTN_SMEM);

    bias_kernel<<<(NBIAS + 255) / 256, 256>>>(mlp_w1, mlp_b1, mlp_w2, mlp_b2);
    conv_all<<<NCHUNK * (MT_QKV + NT_QKV + MT_PROJ), 256>>>(x, qkv_w, proj_w);
    gemm_qkv_mma<<<dim3(NT_QKV, MT_QKV), 256>>>(qkv_b);
    attn_mma<<<dim3(8, NH, BB), 256, ATTN_SMEM>>>();
    gemm_proj_mma<<<dim3(NT_PROJ, MT_PROJ), 256>>>(proj_b, out);
}

// round 12
// speedup vs baseline: 1.0245x; 1.0245x over previous
#include <cuda_runtime.h>
#include <cuda_bf16.h>
#include <math.h>
#include <stdint.h>

#define BB 8
#define CC 384
#define NN 1024
#define NH 8
#define HD 48
#define HID 192
#define NBIAS 3969
#define BIAS_STRIDE 4096
#define QK_SCALE 0.14433756729740643f  // 48^-0.5
#define NCHUNK 18          // K' = 1152 split dim / 64
#define MT_QKV 64
#define NT_QKV 9
#define MT_PROJ 3
#define NT_PROJ 64

// ---------------- PTX helpers ----------------------------------------------
__device__ __forceinline__ uint32_t cvta_smem(const void* p) {
    uint32_t a;
    asm("{ .reg .u64 t; cvta.to.shared.u64 t, %1; cvt.u32.u64 %0, t; }" : "=r"(a) : "l"(p));
    return a;
}
__device__ __forceinline__ void ldsm4(uint32_t &r0, uint32_t &r1, uint32_t &r2,
                                      uint32_t &r3, uint32_t addr) {
    asm volatile("ldmatrix.sync.aligned.m8n8.x4.shared.b16 {%0,%1,%2,%3}, [%4];"
                 : "=r"(r0), "=r"(r1), "=r"(r2), "=r"(r3) : "r"(addr));
}
__device__ __forceinline__ void ldsm4t(uint32_t &r0, uint32_t &r1, uint32_t &r2,
                                       uint32_t &r3, uint32_t addr) {
    asm volatile("ldmatrix.sync.aligned.m8n8.x4.trans.shared.b16 {%0,%1,%2,%3}, [%4];"
                 : "=r"(r0), "=r"(r1), "=r"(r2), "=r"(r3) : "r"(addr));
}
__device__ __forceinline__ void mma16816(float* c, uint32_t a0, uint32_t a1,
                                         uint32_t a2, uint32_t a3,
                                         uint32_t b0, uint32_t b1) {
    asm volatile(
        "mma.sync.aligned.m16n8k16.row.col.f32.bf16.bf16.f32 "
        "{%0,%1,%2,%3}, {%4,%5,%6,%7}, {%8,%9}, {%0,%1,%2,%3};"
        : "+f"(c[0]), "+f"(c[1]), "+f"(c[2]), "+f"(c[3])
        : "r"(a0), "r"(a1), "r"(a2), "r"(a3), "r"(b0), "r"(b1));
}
__device__ __forceinline__ void cp16(uint32_t dst, const void* src) {
    asm volatile("cp.async.cg.shared.global [%0], [%1], 16;" :: "r"(dst), "l"(src));
}
#define CP_COMMIT() asm volatile("cp.async.commit_group;")
#define CP_WAIT0()  asm volatile("cp.async.wait_group 0;")
#define CP_WAIT1()  asm volatile("cp.async.wait_group 1;")

// pack two f32 -> bf16x2 (lo in low half)
__device__ __forceinline__ uint32_t packbf2(float lo, float hi) {
    uint32_t r; asm("cvt.rn.bf16x2.f32 %0, %1, %2;" : "=r"(r) : "f"(hi), "f"(lo)); return r;
}
__device__ __forceinline__ float lo_as_f(uint32_t u) { return __uint_as_float(u << 16); }
__device__ __forceinline__ float hi_as_f(uint32_t u) { return __uint_as_float(u & 0xFFFF0000u); }

// ---------------- scratch globals (zero-init; no runtime alloc) -------------
__device__ float g_bias[NH * BIAS_STRIDE];
// split-bf16 swizzled tile images, [.. tile][split hi/lo][8192 bf16 = 16KB]
__device__ __nv_bfloat16 g_Qt[(size_t)BB*NH*8*2*8192];   // Q, pre-scaled
__device__ __nv_bfloat16 g_Kt[(size_t)BB*NH*8*2*8192];
__device__ __nv_bfloat16 g_Vt[(size_t)BB*NH*8*2*8192];
// GEMM operand images (chunk-major)
__device__ __nv_bfloat16 g_XA[(size_t)MT_QKV * NCHUNK * 8192];   // tokens (hi,hi,lo)
__device__ __nv_bfloat16 g_WQ[(size_t)NT_QKV * NCHUNK * 8192];   // qkv_w^T (hi,lo,hi)
__device__ __nv_bfloat16 g_AT[(size_t)NT_PROJ * NCHUNK * 8192];  // attn out (hi,hi,lo)
__device__ __nv_bfloat16 g_WP[(size_t)MT_PROJ * NCHUNK * 8192];  // proj_w^T (hi,lo,hi)

__device__ __forceinline__ unsigned sw128(unsigned off) {
    return off ^ ((off >> 3) & 0x70);
}
__device__ __forceinline__ uint4 pack8(const unsigned short* h) {
    uint4 u;
    u.x = h[0] | ((unsigned)h[1] << 16);
    u.y = h[2] | ((unsigned)h[3] << 16);
    u.z = h[4] | ((unsigned)h[5] << 16);
    u.w = h[6] | ((unsigned)h[7] << 16);
    return u;
}

// ---------------------------------------------------------------------------
// 1) Relative-bias MLP over the 63x63 unique relative offsets
// ---------------------------------------------------------------------------
__global__ void bias_kernel(const float* __restrict__ w1, const float* __restrict__ b1,
                            const float* __restrict__ w2, const float* __restrict__ b2) {
    int p = blockIdx.x * blockDim.x + threadIdx.x;
    if (p >= NBIAS) return;
    int dh = p / 63, dw = p % 63;
    float rh = (float)(dh - 31) * (1.0f / 31.0f);
    float rw = (float)(dw - 31) * (1.0f / 31.0f);
    float out[NH];
#pragma unroll
    for (int h = 0; h < NH; h++) out[h] = b2[h];
    for (int k = 0; k < HID; k++) {
        float pre = rh * w1[k] + rw * w1[HID + k] + b1[k];
        float g = 0.5f * pre * (1.0f + erff(pre * 0.70710678118654752f));
#pragma unroll
        for (int h = 0; h < NH; h++) out[h] += g * w2[k * NH + h];
    }
#pragma unroll
    for (int h = 0; h < NH; h++) g_bias[h * BIAS_STRIDE + p] = out[h];
}

// ---------------------------------------------------------------------------
// 2) Unified operand-conversion kernel
// ---------------------------------------------------------------------------
__global__ __launch_bounds__(256) void conv_all(const float* __restrict__ x,
                                                const float* __restrict__ qkv_w,
                                                const float* __restrict__ proj_w) {
    int blk = blockIdx.x;
    int role, tile, chunk;
    if (blk < NCHUNK * MT_QKV)            { role = 0; tile = blk / NCHUNK; chunk = blk % NCHUNK; }
    else if (blk < NCHUNK * (MT_QKV + NT_QKV)) {
        int t = blk - NCHUNK * MT_QKV;      role = 1; tile = t / NCHUNK; chunk = t % NCHUNK;
    } else {
        int t = blk - NCHUNK * (MT_QKV + NT_QKV); role = 2; tile = t / NCHUNK; chunk = t % NCHUNK;
    }
    const int term = chunk / 6;
    const int kbase = chunk * 64 - term * 384;

    if (role == 0) {
        const bool lo = (term == 2);
        __nv_bfloat16* dst = g_XA + ((size_t)(tile * NCHUNK + chunk)) * 8192;
        for (int idx = threadIdx.x; idx < 1024; idx += 256) {
            int r = idx & 127, g = idx >> 7;
            int token = tile * 128 + r;
            int b = token >> 10, n = token & 1023;
            const float* s = x + ((size_t)(b * CC + kbase + g * 8)) * NN + n;
            unsigned short hh[8];
#pragma unroll
            for (int j = 0; j < 8; j++) {
                float v = s[(size_t)j * NN];
                __nv_bfloat16 h = __float2bfloat16(v);
                if (lo) h = __float2bfloat16(v - __bfloat162float(h));
                hh[j] = __bfloat16_as_ushort(h);
            }
            *(uint4*)((char*)dst + sw128((unsigned)(r * 128 + g * 16))) = pack8(hh);
        }
    } else {
        const bool lo = (term == 1);
        const float* src = (role == 1) ? qkv_w : proj_w;
        const int ks = (role == 1) ? 3 * CC : CC;
        __nv_bfloat16* dst = ((role == 1) ? g_WQ : g_WP) +
                             ((size_t)(tile * NCHUNK + chunk)) * 8192;
        for (int idx = threadIdx.x; idx < 1024; idx += 256) {
            int r = idx & 127, g = idx >> 7;
            int row = tile * 128 + r;
            const float* s = src + row + (size_t)(kbase + g * 8) * ks;
            unsigned short hh[8];
#pragma unroll
            for (int j = 0; j < 8; j++) {
                float v = s[(size_t)j * ks];
                __nv_bfloat16 h = __float2bfloat16(v);
                if (lo) h = __float2bfloat16(v - __bfloat162float(h));
                hh[j] = __bfloat16_as_ushort(h);
            }
            *(uint4*)((char*)dst + sw128((unsigned)(r * 128 + g * 16))) = pack8(hh);
        }
    }
}

// ---------------------------------------------------------------------------
// 3) cp.async double-buffered mma.sync GEMM mainloop (proven R10)
// ---------------------------------------------------------------------------
__device__ __forceinline__ void mma_mainloop_pipe(const uint4* __restrict__ At,
                                                  const uint4* __restrict__ Bt,
                                                  uint32_t sBase,
                                                  int tid, int warp_m, int warp_n,
                                                  float acc[4][4][4]) {
    const int lane = tid & 31;
    const int lrow = lane & 7;
    const int lmat = lane >> 3;
    const int rA0 = warp_m * 64 + ((lmat & 1) << 3) + lrow;
    const int rB0 = warp_n * 32 + ((lmat & 1) << 3) + lrow;
    const int gHalf = lmat >> 1;

    auto issue = [&](int c, int buf) {
        const uint4* Ac = At + c * 1024;
        const uint4* Bc = Bt + c * 1024;
        uint32_t base = sBase + buf * 32768;
#pragma unroll
        for (int i = tid; i < 1024; i += 256) cp16(base + i * 16, Ac + i);
#pragma unroll
        for (int i = tid; i < 1024; i += 256) cp16(base + 16384 + i * 16, Bc + i);
        CP_COMMIT();
    };

    issue(0, 0);
    for (int c = 0; c < NCHUNK; c++) {
        if (c + 1 < NCHUNK) { issue(c + 1, (c + 1) & 1); CP_WAIT1(); }
        else                { CP_WAIT0(); }
        __syncthreads();
        const uint32_t sA = sBase + (c & 1) * 32768;
        const uint32_t sB = sA + 16384;
#pragma unroll
        for (int ks = 0; ks < 4; ks++) {
            const int g = ks * 2 + gHalf;
            uint32_t a[4][4];
#pragma unroll
            for (int mt = 0; mt < 4; mt++) {
                int row = rA0 + mt * 16;
                uint32_t addr = sA + row * 128 + ((g ^ (row & 7)) << 4);
                ldsm4(a[mt][0], a[mt][1], a[mt][2], a[mt][3], addr);
            }
            uint32_t b[4][2];
#pragma unroll
            for (int np = 0; np < 2; np++) {
                int row = rB0 + np * 16;
                uint32_t addr = sB + row * 128 + ((g ^ (row & 7)) << 4);
                uint32_t r0, r1, r2, r3;
                ldsm4(r0, r1, r2, r3, addr);
                b[2*np][0] = r0; b[2*np][1] = r2;
                b[2*np+1][0] = r1; b[2*np+1][1] = r3;
            }
#pragma unroll
            for (int mt = 0; mt < 4; mt++)
#pragma unroll
                for (int nt = 0; nt < 4; nt++)
                    mma16816(acc[mt][nt], a[mt][0], a[mt][1], a[mt][2], a[mt][3],
                             b[nt][0], b[nt][1]);
        }
        __syncthreads();
    }
}

// qkv GEMM: epilogue writes split-bf16 swizzled Q/K/V tile images.
__global__ __launch_bounds__(256) void gemm_qkv_mma(const float* __restrict__ bias) {
    __shared__ __align__(16) uint4 sbuf[4096];     // 64 KB ping-pong
    const int nTile = blockIdx.x, mTile = blockIdx.y;
    const int tid = threadIdx.x, lane = tid & 31, wid = tid >> 5;
    const int warp_m = wid & 1, warp_n = wid >> 1;

    float acc[4][4][4] = {};
    mma_mainloop_pipe(((const uint4*)g_XA) + (size_t)mTile * NCHUNK * 1024,
                      ((const uint4*)g_WQ) + (size_t)nTile * NCHUNK * 1024,
                      cvta_smem(sbuf), tid, warp_m, warp_n, acc);

    const int which = (nTile * 128) / CC;
    __nv_bfloat16* dst = (which == 0) ? g_Qt : (which == 1 ? g_Kt : g_Vt);
    const float scale = (which == 0) ? QK_SCALE : 1.0f;
    const int rbase = mTile * 128 + warp_m * 64 + (lane >> 2);
    const int cbase = nTile * 128 + warp_n * 32 + (lane & 3) * 2;
#pragma unroll
    for (int nt = 0; nt < 4; nt++) {
        int col = cbase + nt * 8;
        int c = col - which * CC;
        int head = c / HD, d = c - head * HD;
        float2 bb = *(const float2*)&bias[col];
#pragma unroll
        for (int mt = 0; mt < 4; mt++)
#pragma unroll
            for (int half = 0; half < 2; half++) {
                int token = rbase + mt * 16 + half * 8;
                int b = token >> 10, n = token & 1023;
                float vx = (acc[mt][nt][half*2+0] + bb.x) * scale;
                float vy = (acc[mt][nt][half*2+1] + bb.y) * scale;
                uint32_t hp = packbf2(vx, vy);
                uint32_t lp = packbf2(vx - lo_as_f(hp), vy - hi_as_f(hp));
                size_t img = ((size_t)((b * NH + head) * 8 + (n >> 7))) * 2;
                int row = n & 127;
                unsigned off = (unsigned)(row * 128) +
                               ((((unsigned)d >> 3) ^ (row & 7)) << 4) + (d & 7) * 2;
                *(uint32_t*)((char*)(dst + img * 8192) + off) = hp;
                *(uint32_t*)((char*)(dst + (img + 1) * 8192) + off) = lp;
            }
    }
}

// proj GEMM: out[b][c][n]
__global__ __launch_bounds__(256) void gemm_proj_mma(const float* __restrict__ pb,
                                                     float* __restrict__ out) {
    __shared__ __align__(16) uint4 sbuf[4096];
    const int nTile = blockIdx.x, mTile = blockIdx.y;
    const int tid = threadIdx.x, lane = tid & 31, wid = tid >> 5;
    const int warp_m = wid & 1, warp_n = wid >> 1;

    float acc[4][4][4] = {};
    mma_mainloop_pipe(((const uint4*)g_WP) + (size_t)mTile * NCHUNK * 1024,
                      ((const uint4*)g_AT) + (size_t)nTile * NCHUNK * 1024,
                      cvta_smem(sbuf), tid, warp_m, warp_n, acc);

    const int b = (nTile * 128) >> 10;
    const int crow0 = mTile * 128 + warp_m * 64 + (lane >> 2);
    const int tok0  = nTile * 128 + warp_n * 32 + (lane & 3) * 2;
#pragma unroll
    for (int mt = 0; mt < 4; mt++)
#pragma unroll
        for (int half = 0; half < 2; half++) {
            int crow = crow0 + mt * 16 + half * 8;
            float pbv = pb[crow];
            float* orow = out + ((size_t)(b * CC + crow)) * NN;
#pragma unroll
            for (int nt = 0; nt < 4; nt++) {
                int token = tok0 + nt * 8;
                float2 v;
                v.x = acc[mt][nt][half*2+0] + pbv;
                v.y = acc[mt][nt][half*2+1] + pbv;
                *(float2*)(orow + (token & 1023)) = v;
            }
        }
}

// ---------------------------------------------------------------------------
// 4) Tensor-core flash attention, TK=64, 112 KB smem -> 2 CTAs/SM.
//    smem: [0,16K) bias | [16K,48K) Q hi/lo | [48K..) 2 x {Kh,Kl,Vh,Vl} 32KB
// ---------------------------------------------------------------------------
#define ATTN_SMEM (16384 + 32768 + 2 * 32768)   // 112 KB

__global__ __launch_bounds__(256, 2) void attn_mma() {
    extern __shared__ char smem[];
    const int qt = blockIdx.x, h = blockIdx.y, b = blockIdx.z;
    const int tid = threadIdx.x, lane = tid & 31, warp = tid >> 5;
    const uint32_t sb = cvta_smem(smem);
    const uint32_t sQ = sb + 16384, sKV = sb + 49152;
    float* sBiasF = (float*)smem;

    const size_t bh = (size_t)(b * NH + h);

    // load K/V half-image (64 keys) t into buffer buf: [Kh 8K][Kl 8K][Vh 8K][Vl 8K]
    auto loadKV = [&](int t, uint32_t buf) {
        const int img = t >> 1, half = t & 1;
        const char* gK = (const char*)(g_Kt + (bh * 8 + img) * 2 * 8192 + half * 4096);
        const char* gV = (const char*)(g_Vt + (bh * 8 + img) * 2 * 8192 + half * 4096);
        for (int i = tid; i < 512; i += 256) {
            cp16(buf + i * 16,         gK + i * 16);            // Kh
            cp16(buf + 8192 + i * 16,  gK + 16384 + i * 16);    // Kl
            cp16(buf + 16384 + i * 16, gV + i * 16);            // Vh
            cp16(buf + 24576 + i * 16, gV + 16384 + i * 16);    // Vl
        }
        CP_COMMIT();
    };

    {
        const char* gB = (const char*)(g_bias + h * BIAS_STRIDE);
        for (int i = tid; i < 1024; i += 256) cp16(sb + i * 16, gB + i * 16);
        const char* gQ = (const char*)(g_Qt + (bh * 8 + qt) * 2 * 8192);
        for (int i = tid; i < 2048; i += 256) cp16(sQ + i * 16, gQ + i * 16);
        loadKV(0, sKV);
        CP_WAIT0();
        __syncthreads();
    }

    const int lrow = lane & 7, lmat = lane >> 3, gH = lmat >> 1;
    const int rowA = warp * 16 + ((lmat & 1) << 3) + lrow;
    uint32_t aQh[3][4], aQl[3][4];
#pragma unroll
    for (int ks = 0; ks < 3; ks++) {
        int g = 2 * ks + gH;
        uint32_t addr = sQ + rowA * 128 + ((g ^ (rowA & 7)) << 4);
        ldsm4(aQh[ks][0], aQh[ks][1], aQh[ks][2], aQh[ks][3], addr);
        ldsm4(aQl[ks][0], aQl[ks][1], aQl[ks][2], aQl[ks][3], addr + 16384);
    }

    const int q0 = qt * 128 + warp * 16 + (lane >> 2);
    const int q1 = q0 + 8;
    const int ih0 = q0 >> 5, iw0 = q0 & 31;
    const int ih1 = q1 >> 5, iw1 = q1 & 31;

    float Oacc[6][4] = {};
    float m0 = -1e30f, m1 = -1e30f, l0 = 0.0f, l1 = 0.0f;

    for (int kt = 0; kt < 16; kt++) {
        const uint32_t bufc = sKV + (kt & 1) * 32768;
        if (kt < 15) loadKV(kt + 1, sKV + ((kt + 1) & 1) * 32768);
        else         CP_COMMIT();

        // ---- S = Q K^T over 64 keys: 2 kg-pairs -> 4 accumulator chains ----
        float S[8][4];
#pragma unroll
        for (int i = 0; i < 8; i++)
#pragma unroll
            for (int j = 0; j < 4; j++) S[i][j] = 0.0f;

#pragma unroll
        for (int kgp = 0; kgp < 2; kgp++) {
            const int rowB0 = kgp * 32 + ((lmat & 1) << 3) + lrow;
            const int rowB1 = rowB0 + 16;
            float* S0 = S[4*kgp + 0];
            float* S1 = S[4*kgp + 1];
            float* S2 = S[4*kgp + 2];
            float* S3 = S[4*kgp + 3];
#pragma unroll
            for (int ks = 0; ks < 3; ks++) {
                const int g = 2 * ks + gH;
                const uint32_t a0 = bufc + rowB0 * 128 + ((g ^ (rowB0 & 7)) << 4);
                const uint32_t a1 = bufc + rowB1 * 128 + ((g ^ (rowB1 & 7)) << 4);
                uint32_t h00,h01,h02,h03, h10,h11,h12,h13;
                uint32_t l00,l01,l02,l03, l10,l11,l12,l13;
                ldsm4(h00,h01,h02,h03, a0);            // Kh kg0
                ldsm4(h10,h11,h12,h13, a1);            // Kh kg1
                ldsm4(l00,l01,l02,l03, a0 + 8192);     // Kl kg0
                ldsm4(l10,l11,l12,l13, a1 + 8192);     // Kl kg1
                mma16816(S0, aQh[ks][0],aQh[ks][1],aQh[ks][2],aQh[ks][3], h00,h02);
                mma16816(S1, aQh[ks][0],aQh[ks][1],aQh[ks][2],aQh[ks][3], h01,h03);
                mma16816(S2, aQh[ks][0],aQh[ks][1],aQh[ks][2],aQh[ks][3], h10,h12);
                mma16816(S3, aQh[ks][0],aQh[ks][1],aQh[ks][2],aQh[ks][3], h11,h13);
                mma16816(S0, aQl[ks][0],aQl[ks][1],aQl[ks][2],aQl[ks][3], h00,h02);
                mma16816(S1, aQl[ks][0],aQl[ks][1],aQl[ks][2],aQl[ks][3], h01,h03);
                mma16816(S2, aQl[ks][0],aQl[ks][1],aQl[ks][2],aQl[ks][3], h10,h12);
                mma16816(S3, aQl[ks][0],aQl[ks][1],aQl[ks][2],aQl[ks][3], h11,h13);
                mma16816(S0, aQh[ks][0],aQh[ks][1],aQh[ks][2],aQh[ks][3], l00,l02);
                mma16816(S1, aQh[ks][0],aQh[ks][1],aQh[ks][2],aQh[ks][3], l01,l03);
                mma16816(S2, aQh[ks][0],aQh[ks][1],aQh[ks][2],aQh[ks][3], l10,l12);
                mma16816(S3, aQh[ks][0],aQh[ks][1],aQh[ks][2],aQh[ks][3], l11,l13);
            }
        }

        // ---- bias + online softmax over 64 keys ----
        const int kb = kt * 64 + (lane & 3) * 2;
        float tm0 = -1e30f, tm1 = -1e30f;
#pragma unroll
        for (int nb = 0; nb < 8; nb++) {
            int k0 = kb + nb * 8, k1 = k0 + 1;
            int kh0 = k0 >> 5, kw0 = k0 & 31, kh1 = k1 >> 5, kw1 = k1 & 31;
            S[nb][0] += sBiasF[(ih0 - kh0 + 31) * 63 + (iw0 - kw0 + 31)];
            S[nb][1] += sBiasF[(ih0 - kh1 + 31) * 63 + (iw0 - kw1 + 31)];
            S[nb][2] += sBiasF[(ih1 - kh0 + 31) * 63 + (iw1 - kw0 + 31)];
            S[nb][3] += sBiasF[(ih1 - kh1 + 31) * 63 + (iw1 - kw1 + 31)];
            tm0 = fmaxf(tm0, fmaxf(S[nb][0], S[nb][1]));
            tm1 = fmaxf(tm1, fmaxf(S[nb][2], S[nb][3]));
        }
        tm0 = fmaxf(tm0, __shfl_xor_sync(0xFFFFFFFFu, tm0, 1));
        tm0 = fmaxf(tm0, __shfl_xor_sync(0xFFFFFFFFu, tm0, 2));
        tm1 = fmaxf(tm1, __shfl_xor_sync(0xFFFFFFFFu, tm1, 1));
        tm1 = fmaxf(tm1, __shfl_xor_sync(0xFFFFFFFFu, tm1, 2));
        float mn0 = fmaxf(m0, tm0), mn1 = fmaxf(m1, tm1);
        float al0 = __expf(m0 - mn0), al1 = __expf(m1 - mn1);
        m0 = mn0; m1 = mn1;
        l0 *= al0; l1 *= al1;
#pragma unroll
        for (int nb = 0; nb < 6; nb++) {
            Oacc[nb][0] *= al0; Oacc[nb][1] *= al0;
            Oacc[nb][2] *= al1; Oacc[nb][3] *= al1;
        }
        float ls0 = 0.0f, ls1 = 0.0f;
#pragma unroll
        for (int nb = 0; nb < 8; nb++) {
            S[nb][0] = __expf(S[nb][0] - m0); ls0 += S[nb][0];
            S[nb][1] = __expf(S[nb][1] - m0); ls0 += S[nb][1];
            S[nb][2] = __expf(S[nb][2] - m1); ls1 += S[nb][2];
            S[nb][3] = __expf(S[nb][3] - m1); ls1 += S[nb][3];
        }
        l0 += ls0; l1 += ls1;

        // ---- O += P V over 64 keys ----
#pragma unroll
        for (int kg = 0; kg < 4; kg++) {
            uint32_t pa0 = packbf2(S[2*kg][0],   S[2*kg][1]);
            uint32_t pa1 = packbf2(S[2*kg][2],   S[2*kg][3]);
            uint32_t pa2 = packbf2(S[2*kg+1][0], S[2*kg+1][1]);
            uint32_t pa3 = packbf2(S[2*kg+1][2], S[2*kg+1][3]);
            uint32_t qa0 = packbf2(S[2*kg][0]   - lo_as_f(pa0), S[2*kg][1]   - hi_as_f(pa0));
            uint32_t qa1 = packbf2(S[2*kg][2]   - lo_as_f(pa1), S[2*kg][3]   - hi_as_f(pa1));
            uint32_t qa2 = packbf2(S[2*kg+1][0] - lo_as_f(pa2), S[2*kg+1][1] - hi_as_f(pa2));
            uint32_t qa3 = packbf2(S[2*kg+1][2] - lo_as_f(pa3), S[2*kg+1][3] - hi_as_f(pa3));
            const int rowV = kg * 16 + (lane & 15);
            uint32_t vh[3][4], vl[3][4];
#pragma unroll
            for (int dp = 0; dp < 3; dp++) {
                int g = dp * 2 + (lane >> 4);
                uint32_t addr = bufc + 16384 + rowV * 128 + ((g ^ (rowV & 7)) << 4);
                ldsm4t(vh[dp][0], vh[dp][1], vh[dp][2], vh[dp][3], addr);
                ldsm4t(vl[dp][0], vl[dp][1], vl[dp][2], vl[dp][3], addr + 8192);
            }
#pragma unroll
            for (int dp = 0; dp < 3; dp++) {
                mma16816(Oacc[2*dp],   pa0, pa1, pa2, pa3, vh[dp][0], vh[dp][1]);
                mma16816(Oacc[2*dp+1], pa0, pa1, pa2, pa3, vh[dp][2], vh[dp][3]);
            }
#pragma unroll
            for (int dp = 0; dp < 3; dp++) {
                mma16816(Oacc[2*dp],   qa0, qa1, qa2, qa3, vh[dp][0], vh[dp][1]);
                mma16816(Oacc[2*dp+1], qa0, qa1, qa2, qa3, vh[dp][2], vh[dp][3]);
            }
#pragma unroll
            for (int dp = 0; dp < 3; dp++) {
                mma16816(Oacc[2*dp],   pa0, pa1, pa2, pa3, vl[dp][0], vl[dp][1]);
                mma16816(Oacc[2*dp+1], pa0, pa1, pa2, pa3, vl[dp][2], vl[dp][3]);
            }
        }

        CP_WAIT0();
        __syncthreads();
    }

    l0 += __shfl_xor_sync(0xFFFFFFFFu, l0, 1);
    l0 += __shfl_xor_sync(0xFFFFFFFFu, l0, 2);
    l1 += __shfl_xor_sync(0xFFFFFFFFu, l1, 1);
    l1 += __shfl_xor_sync(0xFFFFFFFFu, l1, 2);
    const float inv0 = 1.0f / l0, inv1 = 1.0f / l1;

    const int token0 = b * NN + q0;
    const size_t tbase = (size_t)(token0 >> 7) * NCHUNK;
    const int row0 = token0 & 127;
#pragma unroll
    for (int nb = 0; nb < 6; nb++) {
        int d = nb * 8 + (lane & 3) * 2;
        int c = h * HD + d;
        int c6 = c >> 6;
        unsigned colc = (unsigned)(c & 63);
#pragma unroll
        for (int half = 0; half < 2; half++) {
            int row = row0 + half * 8;
            float vx = (half == 0 ? Oacc[nb][0] * inv0 : Oacc[nb][2] * inv1);
            float vy = (half == 0 ? Oacc[nb][1] * inv0 : Oacc[nb][3] * inv1);
            uint32_t hp = packbf2(vx, vy);
            uint32_t lp = packbf2(vx - lo_as_f(hp), vy - hi_as_f(hp));
            unsigned off = (unsigned)(row * 128) +
                           (((colc >> 3) ^ (row & 7)) << 4) + (colc & 7) * 2;
            *(uint32_t*)((char*)(g_AT + (tbase + c6) * 8192) + off) = hp;
            *(uint32_t*)((char*)(g_AT + (tbase + 6 + c6) * 8192) + off) = hp;
            *(uint32_t*)((char*)(g_AT + (tbase + 12 + c6) * 8192) + off) = lp;
        }
    }
}

// ---------------------------------------------------------------------------
extern "C" void kernel_launch(void* const* d_in, const int* in_sizes, int n_in,
                              void* d_out, int out_size) {
    const float* x      = (const float*)d_in[0];
    const float* qkv_w  = (const float*)d_in[1];
    const float* qkv_b  = (const float*)d_in[2];
    const float* proj_w = (const float*)d_in[3];
    const float* proj_b = (const float*)d_in[4];
    const float* mlp_w1 = (const float*)d_in[5];
    const float* mlp_b1 = (const float*)d_in[6];
    const float* mlp_w2 = (const float*)d_in[7];
    const float* mlp_b2 = (const float*)d_in[8];
    float* out = (float*)d_out;

    cudaFuncSetAttribute(attn_mma, cudaFuncAttributeMaxDynamicSharedMemorySize, ATTN_SMEM);

    bias_kernel<<<(NBIAS + 255) / 256, 256>>>(mlp_w1, mlp_b1, mlp_w2, mlp_b2);
    conv_all<<<NCHUNK * (MT_QKV + NT_QKV + MT_PROJ), 256>>>(x, qkv_w, proj_w);
    gemm_qkv_mma<<<dim3(NT_QKV, MT_QKV), 256>>>(qkv_b);
    attn_mma<<<dim3(8, NH, BB), 256, ATTN_SMEM>>>();
    gemm_proj_mma<<<dim3(NT_PROJ, MT_PROJ), 256>>>(proj_b, out);
}

// round 17
// speedup vs baseline: 1.0591x; 1.0338x over previous
#include <cuda_runtime.h>
#include <cuda_bf16.h>
#include <math.h>
#include <stdint.h>

#define BB 8
#define CC 384
#define NN 1024
#define NH 8
#define HD 48
#define HID 192
#define NBIAS 3969
#define BIAS_STRIDE 4096
#define LOG2E 1.4426950408889634f
#define QK_SCALE 0.14433756729740643f  // 48^-0.5 (log2e folded in at use site)
#define NCHUNK 18          // K' = 1152 split dim / 64
#define MT_QKV 64
#define NT_QKV 9
#define MT_PROJ 3
#define NT_PROJ 64

// ---------------- PTX helpers ----------------------------------------------
__device__ __forceinline__ uint32_t cvta_smem(const void* p) {
    uint32_t a;
    asm("{ .reg .u64 t; cvta.to.shared.u64 t, %1; cvt.u32.u64 %0, t; }" : "=r"(a) : "l"(p));
    return a;
}
__device__ __forceinline__ void ldsm4(uint32_t &r0, uint32_t &r1, uint32_t &r2,
                                      uint32_t &r3, uint32_t addr) {
    asm volatile("ldmatrix.sync.aligned.m8n8.x4.shared.b16 {%0,%1,%2,%3}, [%4];"
                 : "=r"(r0), "=r"(r1), "=r"(r2), "=r"(r3) : "r"(addr));
}
__device__ __forceinline__ void ldsm4t(uint32_t &r0, uint32_t &r1, uint32_t &r2,
                                       uint32_t &r3, uint32_t addr) {
    asm volatile("ldmatrix.sync.aligned.m8n8.x4.trans.shared.b16 {%0,%1,%2,%3}, [%4];"
                 : "=r"(r0), "=r"(r1), "=r"(r2), "=r"(r3) : "r"(addr));
}
__device__ __forceinline__ void mma16816(float* c, uint32_t a0, uint32_t a1,
                                         uint32_t a2, uint32_t a3,
                                         uint32_t b0, uint32_t b1) {
    asm volatile(
        "mma.sync.aligned.m16n8k16.row.col.f32.bf16.bf16.f32 "
        "{%0,%1,%2,%3}, {%4,%5,%6,%7}, {%8,%9}, {%0,%1,%2,%3};"
        : "+f"(c[0]), "+f"(c[1]), "+f"(c[2]), "+f"(c[3])
        : "r"(a0), "r"(a1), "r"(a2), "r"(a3), "r"(b0), "r"(b1));
}
__device__ __forceinline__ void cp16(uint32_t dst, const void* src) {
    asm volatile("cp.async.cg.shared.global [%0], [%1], 16;" :: "r"(dst), "l"(src));
}
#define CP_COMMIT() asm volatile("cp.async.commit_group;")
#define CP_WAIT0()  asm volatile("cp.async.wait_group 0;")
#define CP_WAIT1()  asm volatile("cp.async.wait_group 1;")

// raw exp2 (MUFU.EX2), same accuracy class as __expf
__device__ __forceinline__ float ex2f(float x) {
    float r; asm("ex2.approx.f32 %0, %1;" : "=f"(r) : "f"(x)); return r;
}

// pack two f32 -> bf16x2 (lo in low half)
__device__ __forceinline__ uint32_t packbf2(float lo, float hi) {
    uint32_t r; asm("cvt.rn.bf16x2.f32 %0, %1, %2;" : "=r"(r) : "f"(hi), "f"(lo)); return r;
}
__device__ __forceinline__ float lo_as_f(uint32_t u) { return __uint_as_float(u << 16); }
__device__ __forceinline__ float hi_as_f(uint32_t u) { return __uint_as_float(u & 0xFFFF0000u); }

// ---------------- scratch globals (zero-init; no runtime alloc) -------------
__device__ float g_bias[NH * BIAS_STRIDE];     // pre-scaled by log2e
// split-bf16 swizzled tile images, [.. tile][split hi/lo][8192 bf16 = 16KB]
__device__ __nv_bfloat16 g_Qt[(size_t)BB*NH*8*2*8192];   // Q, pre-scaled by d^-1/2*log2e
__device__ __nv_bfloat16 g_Kt[(size_t)BB*NH*8*2*8192];
__device__ __nv_bfloat16 g_Vt[(size_t)BB*NH*8*2*8192];
// GEMM operand images (chunk-major)
__device__ __nv_bfloat16 g_XA[(size_t)MT_QKV * NCHUNK * 8192];   // tokens (hi,hi,lo)
__device__ __nv_bfloat16 g_WQ[(size_t)NT_QKV * NCHUNK * 8192];   // qkv_w^T (hi,lo,hi)
__device__ __nv_bfloat16 g_AT[(size_t)NT_PROJ * NCHUNK * 8192];  // attn out (hi,hi,lo)
__device__ __nv_bfloat16 g_WP[(size_t)MT_PROJ * NCHUNK * 8192];  // proj_w^T (hi,lo,hi)

__device__ __forceinline__ unsigned sw128(unsigned off) {
    return off ^ ((off >> 3) & 0x70);
}
__device__ __forceinline__ uint4 pack8(const unsigned short* h) {
    uint4 u;
    u.x = h[0] | ((unsigned)h[1] << 16);
    u.y = h[2] | ((unsigned)h[3] << 16);
    u.z = h[4] | ((unsigned)h[5] << 16);
    u.w = h[6] | ((unsigned)h[7] << 16);
    return u;
}

// ---------------------------------------------------------------------------
// 1) Relative-bias MLP; output pre-scaled by log2e for exp2-softmax
// ---------------------------------------------------------------------------
__global__ void bias_kernel(const float* __restrict__ w1, const float* __restrict__ b1,
                            const float* __restrict__ w2, const float* __restrict__ b2) {
    int p = blockIdx.x * blockDim.x + threadIdx.x;
    if (p >= NBIAS) return;
    int dh = p / 63, dw = p % 63;
    float rh = (float)(dh - 31) * (1.0f / 31.0f);
    float rw = (float)(dw - 31) * (1.0f / 31.0f);
    float out[NH];
#pragma unroll
    for (int h = 0; h < NH; h++) out[h] = b2[h];
    for (int k = 0; k < HID; k++) {
        float pre = rh * w1[k] + rw * w1[HID + k] + b1[k];
        float g = 0.5f * pre * (1.0f + erff(pre * 0.70710678118654752f));
#pragma unroll
        for (int h = 0; h < NH; h++) out[h] += g * w2[k * NH + h];
    }
#pragma unroll
    for (int h = 0; h < NH; h++) g_bias[h * BIAS_STRIDE + p] = out[h] * LOG2E;
}

// ---------------------------------------------------------------------------
// 2) Unified operand-conversion kernel
// ---------------------------------------------------------------------------
__global__ __launch_bounds__(256) void conv_all(const float* __restrict__ x,
                                                const float* __restrict__ qkv_w,
                                                const float* __restrict__ proj_w) {
    int blk = blockIdx.x;
    int role, tile, chunk;
    if (blk < NCHUNK * MT_QKV)            { role = 0; tile = blk / NCHUNK; chunk = blk % NCHUNK; }
    else if (blk < NCHUNK * (MT_QKV + NT_QKV)) {
        int t = blk - NCHUNK * MT_QKV;      role = 1; tile = t / NCHUNK; chunk = t % NCHUNK;
    } else {
        int t = blk - NCHUNK * (MT_QKV + NT_QKV); role = 2; tile = t / NCHUNK; chunk = t % NCHUNK;
    }
    const int term = chunk / 6;
    const int kbase = chunk * 64 - term * 384;

    if (role == 0) {
        const bool lo = (term == 2);
        __nv_bfloat16* dst = g_XA + ((size_t)(tile * NCHUNK + chunk)) * 8192;
        for (int idx = threadIdx.x; idx < 1024; idx += 256) {
            int r = idx & 127, g = idx >> 7;
            int token = tile * 128 + r;
            int b = token >> 10, n = token & 1023;
            const float* s = x + ((size_t)(b * CC + kbase + g * 8)) * NN + n;
            unsigned short hh[8];
#pragma unroll
            for (int j = 0; j < 8; j++) {
                float v = s[(size_t)j * NN];
                __nv_bfloat16 h = __float2bfloat16(v);
                if (lo) h = __float2bfloat16(v - __bfloat162float(h));
                hh[j] = __bfloat16_as_ushort(h);
            }
            *(uint4*)((char*)dst + sw128((unsigned)(r * 128 + g * 16))) = pack8(hh);
        }
    } else {
        const bool lo = (term == 1);
        const float* src = (role == 1) ? qkv_w : proj_w;
        const int ks = (role == 1) ? 3 * CC : CC;
        __nv_bfloat16* dst = ((role == 1) ? g_WQ : g_WP) +
                             ((size_t)(tile * NCHUNK + chunk)) * 8192;
        for (int idx = threadIdx.x; idx < 1024; idx += 256) {
            int r = idx & 127, g = idx >> 7;
            int row = tile * 128 + r;
            const float* s = src + row + (size_t)(kbase + g * 8) * ks;
            unsigned short hh[8];
#pragma unroll
            for (int j = 0; j < 8; j++) {
                float v = s[(size_t)j * ks];
                __nv_bfloat16 h = __float2bfloat16(v);
                if (lo) h = __float2bfloat16(v - __bfloat162float(h));
                hh[j] = __bfloat16_as_ushort(h);
            }
            *(uint4*)((char*)dst + sw128((unsigned)(r * 128 + g * 16))) = pack8(hh);
        }
    }
}

// ---------------------------------------------------------------------------
// 3) cp.async double-buffered mma.sync GEMM mainloop (proven R10)
// ---------------------------------------------------------------------------
__device__ __forceinline__ void mma_mainloop_pipe(const uint4* __restrict__ At,
                                                  const uint4* __restrict__ Bt,
                                                  uint32_t sBase,
                                                  int tid, int warp_m, int warp_n,
                                                  float acc[4][4][4]) {
    const int lane = tid & 31;
    const int lrow = lane & 7;
    const int lmat = lane >> 3;
    const int rA0 = warp_m * 64 + ((lmat & 1) << 3) + lrow;
    const int rB0 = warp_n * 32 + ((lmat & 1) << 3) + lrow;
    const int gHalf = lmat >> 1;

    auto issue = [&](int c, int buf) {
        const uint4* Ac = At + c * 1024;
        const uint4* Bc = Bt + c * 1024;
        uint32_t base = sBase + buf * 32768;
#pragma unroll
        for (int i = tid; i < 1024; i += 256) cp16(base + i * 16, Ac + i);
#pragma unroll
        for (int i = tid; i < 1024; i += 256) cp16(base + 16384 + i * 16, Bc + i);
        CP_COMMIT();
    };

    issue(0, 0);
    for (int c = 0; c < NCHUNK; c++) {
        if (c + 1 < NCHUNK) { issue(c + 1, (c + 1) & 1); CP_WAIT1(); }
        else                { CP_WAIT0(); }
        __syncthreads();
        const uint32_t sA = sBase + (c & 1) * 32768;
        const uint32_t sB = sA + 16384;
#pragma unroll
        for (int ks = 0; ks < 4; ks++) {
            const int g = ks * 2 + gHalf;
            uint32_t a[4][4];
#pragma unroll
            for (int mt = 0; mt < 4; mt++) {
                int row = rA0 + mt * 16;
                uint32_t addr = sA + row * 128 + ((g ^ (row & 7)) << 4);
                ldsm4(a[mt][0], a[mt][1], a[mt][2], a[mt][3], addr);
            }
            uint32_t b[4][2];
#pragma unroll
            for (int np = 0; np < 2; np++) {
                int row = rB0 + np * 16;
                uint32_t addr = sB + row * 128 + ((g ^ (row & 7)) << 4);
                uint32_t r0, r1, r2, r3;
                ldsm4(r0, r1, r2, r3, addr);
                b[2*np][0] = r0; b[2*np][1] = r2;
                b[2*np+1][0] = r1; b[2*np+1][1] = r3;
            }
#pragma unroll
            for (int mt = 0; mt < 4; mt++)
#pragma unroll
                for (int nt = 0; nt < 4; nt++)
                    mma16816(acc[mt][nt], a[mt][0], a[mt][1], a[mt][2], a[mt][3],
                             b[nt][0], b[nt][1]);
        }
        __syncthreads();
    }
}

// qkv GEMM: epilogue writes split-bf16 swizzled Q/K/V tile images.
__global__ __launch_bounds__(256) void gemm_qkv_mma(const float* __restrict__ bias) {
    __shared__ __align__(16) uint4 sbuf[4096];     // 64 KB ping-pong
    const int nTile = blockIdx.x, mTile = blockIdx.y;
    const int tid = threadIdx.x, lane = tid & 31, wid = tid >> 5;
    const int warp_m = wid & 1, warp_n = wid >> 1;

    float acc[4][4][4] = {};
    mma_mainloop_pipe(((const uint4*)g_XA) + (size_t)mTile * NCHUNK * 1024,
                      ((const uint4*)g_WQ) + (size_t)nTile * NCHUNK * 1024,
                      cvta_smem(sbuf), tid, warp_m, warp_n, acc);

    const int which = (nTile * 128) / CC;
    __nv_bfloat16* dst = (which == 0) ? g_Qt : (which == 1 ? g_Kt : g_Vt);
    const float scale = (which == 0) ? (QK_SCALE * LOG2E) : 1.0f;
    const int rbase = mTile * 128 + warp_m * 64 + (lane >> 2);
    const int cbase = nTile * 128 + warp_n * 32 + (lane & 3) * 2;
#pragma unroll
    for (int nt = 0; nt < 4; nt++) {
        int col = cbase + nt * 8;
        int c = col - which * CC;
        int head = c / HD, d = c - head * HD;
        float2 bb = *(const float2*)&bias[col];
#pragma unroll
        for (int mt = 0; mt < 4; mt++)
#pragma unroll
            for (int half = 0; half < 2; half++) {
                int token = rbase + mt * 16 + half * 8;
                int b = token >> 10, n = token & 1023;
                float vx = (acc[mt][nt][half*2+0] + bb.x) * scale;
                float vy = (acc[mt][nt][half*2+1] + bb.y) * scale;
                uint32_t hp = packbf2(vx, vy);
                uint32_t lp = packbf2(vx - lo_as_f(hp), vy - hi_as_f(hp));
                size_t img = ((size_t)((b * NH + head) * 8 + (n >> 7))) * 2;
                int row = n & 127;
                unsigned off = (unsigned)(row * 128) +
                               ((((unsigned)d >> 3) ^ (row & 7)) << 4) + (d & 7) * 2;
                *(uint32_t*)((char*)(dst + img * 8192) + off) = hp;
                *(uint32_t*)((char*)(dst + (img + 1) * 8192) + off) = lp;
            }
    }
}

// proj GEMM: out[b][c][n]
__global__ __launch_bounds__(256) void gemm_proj_mma(const float* __restrict__ pb,
                                                     float* __restrict__ out) {
    __shared__ __align__(16) uint4 sbuf[4096];
    const int nTile = blockIdx.x, mTile = blockIdx.y;
    const int tid = threadIdx.x, lane = tid & 31, wid = tid >> 5;
    const int warp_m = wid & 1, warp_n = wid >> 1;

    float acc[4][4][4] = {};
    mma_mainloop_pipe(((const uint4*)g_WP) + (size_t)mTile * NCHUNK * 1024,
                      ((const uint4*)g_AT) + (size_t)nTile * NCHUNK * 1024,
                      cvta_smem(sbuf), tid, warp_m, warp_n, acc);

    const int b = (nTile * 128) >> 10;
    const int crow0 = mTile * 128 + warp_m * 64 + (lane >> 2);
    const int tok0  = nTile * 128 + warp_n * 32 + (lane & 3) * 2;
#pragma unroll
    for (int mt = 0; mt < 4; mt++)
#pragma unroll
        for (int half = 0; half < 2; half++) {
            int crow = crow0 + mt * 16 + half * 8;
            float pbv = pb[crow];
            float* orow = out + ((size_t)(b * CC + crow)) * NN;
#pragma unroll
            for (int nt = 0; nt < 4; nt++) {
                int token = tok0 + nt * 8;
                float2 v;
                v.x = acc[mt][nt][half*2+0] + pbv;
                v.y = acc[mt][nt][half*2+1] + pbv;
                *(float2*)(orow + (token & 1023)) = v;
            }
        }
}

// ---------------------------------------------------------------------------
// 4) Tensor-core flash attention, TK=64, 2 CTAs/SM, bias-as-S-init + exp2.
//    smem: [0,16K) bias | [16K,48K) Q hi/lo | [48K..) 2 x {Kh,Kl,Vh,Vl} 32KB
// ---------------------------------------------------------------------------
#define ATTN_SMEM (16384 + 32768 + 2 * 32768)   // 112 KB

__global__ __launch_bounds__(256, 2) void attn_mma() {
    extern __shared__ char smem[];
    const int qt = blockIdx.x, h = blockIdx.y, b = blockIdx.z;
    const int tid = threadIdx.x, lane = tid & 31, warp = tid >> 5;
    const uint32_t sb = cvta_smem(smem);
    const uint32_t sQ = sb + 16384, sKV = sb + 49152;
    float* sBiasF = (float*)smem;

    const size_t bh = (size_t)(b * NH + h);

    // load K/V half-image (64 keys) t into buffer buf: [Kh 8K][Kl 8K][Vh 8K][Vl 8K]
    auto loadKV = [&](int t, uint32_t buf) {
        const int img = t >> 1, half = t & 1;
        const char* gK = (const char*)(g_Kt + (bh * 8 + img) * 2 * 8192 + half * 4096);
        const char* gV = (const char*)(g_Vt + (bh * 8 + img) * 2 * 8192 + half * 4096);
        for (int i = tid; i < 512; i += 256) {
            cp16(buf + i * 16,         gK + i * 16);            // Kh
            cp16(buf + 8192 + i * 16,  gK + 16384 + i * 16);    // Kl
            cp16(buf + 16384 + i * 16, gV + i * 16);            // Vh
            cp16(buf + 24576 + i * 16, gV + 16384 + i * 16);    // Vl
        }
        CP_COMMIT();
    };

    {
        const char* gB = (const char*)(g_bias + h * BIAS_STRIDE);
        for (int i = tid; i < 1024; i += 256) cp16(sb + i * 16, gB + i * 16);
        const char* gQ = (const char*)(g_Qt + (bh * 8 + qt) * 2 * 8192);
        for (int i = tid; i < 2048; i += 256) cp16(sQ + i * 16, gQ + i * 16);
        loadKV(0, sKV);
        CP_WAIT0();
        __syncthreads();
    }

    const int lrow = lane & 7, lmat = lane >> 3, gH = lmat >> 1;
    const int rowA = warp * 16 + ((lmat & 1) << 3) + lrow;
    uint32_t aQh[3][4], aQl[3][4];
#pragma unroll
    for (int ks = 0; ks < 3; ks++) {
        int g = 2 * ks + gH;
        uint32_t addr = sQ + rowA * 128 + ((g ^ (rowA & 7)) << 4);
        ldsm4(aQh[ks][0], aQh[ks][1], aQh[ks][2], aQh[ks][3], addr);
        ldsm4(aQl[ks][0], aQl[ks][1], aQl[ks][2], aQl[ks][3], addr + 16384);
    }

    const int q0 = qt * 128 + warp * 16 + (lane >> 2);
    const int q1 = q0 + 8;
    const int ih0 = q0 >> 5, iw0 = q0 & 31;
    const int ih1 = q1 >> 5, iw1 = q1 & 31;
    // per-thread bias row bases (kwl = (lane&3)*2 pre-subtracted)
    const int Bq0 = (ih0 + 31) * 63 + (iw0 + 31) - (lane & 3) * 2;
    const int Bq1 = (ih1 + 31) * 63 + (iw1 + 31) - (lane & 3) * 2;

    float Oacc[6][4] = {};
    float m0 = -1e30f, m1 = -1e30f, l0 = 0.0f, l1 = 0.0f;

    for (int kt = 0; kt < 16; kt++) {
        const uint32_t bufc = sKV + (kt & 1) * 32768;
        if (kt < 15) loadKV(kt + 1, sKV + ((kt + 1) & 1) * 32768);
        else         CP_COMMIT();

        // ---- S initialized from bias table (keys span rows 2kt, 2kt+1) ----
        float S[8][4];
        {
            const float* r0q0 = sBiasF + (Bq0 - 2 * kt * 63);
            const float* r0q1 = sBiasF + (Bq1 - 2 * kt * 63);
#pragma unroll
            for (int nb = 0; nb < 8; nb++) {
                const float* p0 = (nb < 4) ? r0q0 : (r0q0 - 63);
                const float* p1 = (nb < 4) ? r0q1 : (r0q1 - 63);
                const int o = (nb & 3) * 8;
                S[nb][0] = p0[-o];
                S[nb][1] = p0[-o - 1];
                S[nb][2] = p1[-o];
                S[nb][3] = p1[-o - 1];
            }
        }

        // ---- S += Q K^T over 64 keys: 2 kg-pairs -> 4 accumulator chains ----
#pragma unroll
        for (int kgp = 0; kgp < 2; kgp++) {
            const int rowB0 = kgp * 32 + ((lmat & 1) << 3) + lrow;
            const int rowB1 = rowB0 + 16;
            float* S0 = S[4*kgp + 0];
            float* S1 = S[4*kgp + 1];
            float* S2 = S[4*kgp + 2];
            float* S3 = S[4*kgp + 3];
#pragma unroll
            for (int ks = 0; ks < 3; ks++) {
                const int g = 2 * ks + gH;
                const uint32_t a0 = bufc + rowB0 * 128 + ((g ^ (rowB0 & 7)) << 4);
                const uint32_t a1 = bufc + rowB1 * 128 + ((g ^ (rowB1 & 7)) << 4);
                uint32_t h00,h01,h02,h03, h10,h11,h12,h13;
                uint32_t l00,l01,l02,l03, l10,l11,l12,l13;
                ldsm4(h00,h01,h02,h03, a0);            // Kh kg0
                ldsm4(h10,h11,h12,h13, a1);            // Kh kg1
                ldsm4(l00,l01,l02,l03, a0 + 8192);     // Kl kg0
                ldsm4(l10,l11,l12,l13, a1 + 8192);     // Kl kg1
                mma16816(S0, aQh[ks][0],aQh[ks][1],aQh[ks][2],aQh[ks][3], h00,h02);
                mma16816(S1, aQh[ks][0],aQh[ks][1],aQh[ks][2],aQh[ks][3], h01,h03);
                mma16816(S2, aQh[ks][0],aQh[ks][1],aQh[ks][2],aQh[ks][3], h10,h12);
                mma16816(S3, aQh[ks][0],aQh[ks][1],aQh[ks][2],aQh[ks][3], h11,h13);
                mma16816(S0, aQl[ks][0],aQl[ks][1],aQl[ks][2],aQl[ks][3], h00,h02);
                mma16816(S1, aQl[ks][0],aQl[ks][1],aQl[ks][2],aQl[ks][3], h01,h03);
                mma16816(S2, aQl[ks][0],aQl[ks][1],aQl[ks][2],aQl[ks][3], h10,h12);
                mma16816(S3, aQl[ks][0],aQl[ks][1],aQl[ks][2],aQl[ks][3], h11,h13);
                mma16816(S0, aQh[ks][0],aQh[ks][1],aQh[ks][2],aQh[ks][3], l00,l02);
                mma16816(S1, aQh[ks][0],aQh[ks][1],aQh[ks][2],aQh[ks][3], l01,l03);
                mma16816(S2, aQh[ks][0],aQh[ks][1],aQh[ks][2],aQh[ks][3], l10,l12);
                mma16816(S3, aQh[ks][0],aQh[ks][1],aQh[ks][2],aQh[ks][3], l11,l13);
            }
        }

        // ---- online softmax (exp2 domain) ----
        float tm0 = -1e30f, tm1 = -1e30f;
#pragma unroll
        for (int nb = 0; nb < 8; nb++) {
            tm0 = fmaxf(tm0, fmaxf(S[nb][0], S[nb][1]));
            tm1 = fmaxf(tm1, fmaxf(S[nb][2], S[nb][3]));
        }
        tm0 = fmaxf(tm0, __shfl_xor_sync(0xFFFFFFFFu, tm0, 1));
        tm0 = fmaxf(tm0, __shfl_xor_sync(0xFFFFFFFFu, tm0, 2));
        tm1 = fmaxf(tm1, __shfl_xor_sync(0xFFFFFFFFu, tm1, 1));
        tm1 = fmaxf(tm1, __shfl_xor_sync(0xFFFFFFFFu, tm1, 2));
        if (tm0 > m0 || tm1 > m1) {            // new row max -> rescale
            float mn0 = fmaxf(m0, tm0), mn1 = fmaxf(m1, tm1);
            float al0 = ex2f(m0 - mn0), al1 = ex2f(m1 - mn1);
            m0 = mn0; m1 = mn1;
            l0 *= al0; l1 *= al1;
#pragma unroll
            for (int nb = 0; nb < 6; nb++) {
                Oacc[nb][0] *= al0; Oacc[nb][1] *= al0;
                Oacc[nb][2] *= al1; Oacc[nb][3] *= al1;
            }
        }
        float ls0 = 0.0f, ls1 = 0.0f;
#pragma unroll
        for (int nb = 0; nb < 8; nb++) {
            S[nb][0] = ex2f(S[nb][0] - m0); ls0 += S[nb][0];
            S[nb][1] = ex2f(S[nb][1] - m0); ls0 += S[nb][1];
            S[nb][2] = ex2f(S[nb][2] - m1); ls1 += S[nb][2];
            S[nb][3] = ex2f(S[nb][3] - m1); ls1 += S[nb][3];
        }
        l0 += ls0; l1 += ls1;

        // ---- O += P V over 64 keys ----
#pragma unroll
        for (int kg = 0; kg < 4; kg++) {
            uint32_t pa0 = packbf2(S[2*kg][0],   S[2*kg][1]);
            uint32_t pa1 = packbf2(S[2*kg][2],   S[2*kg][3]);
            uint32_t pa2 = packbf2(S[2*kg+1][0], S[2*kg+1][1]);
            uint32_t pa3 = packbf2(S[2*kg+1][2], S[2*kg+1][3]);
            uint32_t qa0 = packbf2(S[2*kg][0]   - lo_as_f(pa0), S[2*kg][1]   - hi_as_f(pa0));
            uint32_t qa1 = packbf2(S[2*kg][2]   - lo_as_f(pa1), S[2*kg][3]   - hi_as_f(pa1));
            uint32_t qa2 = packbf2(S[2*kg+1][0] - lo_as_f(pa2), S[2*kg+1][1] - hi_as_f(pa2));
            uint32_t qa3 = packbf2(S[2*kg+1][2] - lo_as_f(pa3), S[2*kg+1][3] - hi_as_f(pa3));
            const int rowV = kg * 16 + (lane & 15);
            uint32_t vh[3][4], vl[3][4];
#pragma unroll
            for (int dp = 0; dp < 3; dp++) {
                int g = dp * 2 + (lane >> 4);
                uint32_t addr = bufc + 16384 + rowV * 128 + ((g ^ (rowV & 7)) << 4);
                ldsm4t(vh[dp][0], vh[dp][1], vh[dp][2], vh[dp][3], addr);
                ldsm4t(vl[dp][0], vl[dp][1], vl[dp][2], vl[dp][3], addr + 8192);
            }
#pragma unroll
            for (int dp = 0; dp < 3; dp++) {
                mma16816(Oacc[2*dp],   pa0, pa1, pa2, pa3, vh[dp][0], vh[dp][1]);
                mma16816(Oacc[2*dp+1], pa0, pa1, pa2, pa3, vh[dp][2], vh[dp][3]);
            }
#pragma unroll
            for (int dp = 0; dp < 3; dp++) {
                mma16816(Oacc[2*dp],   qa0, qa1, qa2, qa3, vh[dp][0], vh[dp][1]);
                mma16816(Oacc[2*dp+1], qa0, qa1, qa2, qa3, vh[dp][2], vh[dp][3]);
            }
#pragma unroll
            for (int dp = 0; dp < 3; dp++) {
                mma16816(Oacc[2*dp],   pa0, pa1, pa2, pa3, vl[dp][0], vl[dp][1]);
                mma16816(Oacc[2*dp+1], pa0, pa1, pa2, pa3, vl[dp][2], vl[dp][3]);
            }
        }

        CP_WAIT0();
        __syncthreads();
    }

    l0 += __shfl_xor_sync(0xFFFFFFFFu, l0, 1);
    l0 += __shfl_xor_sync(0xFFFFFFFFu, l0, 2);
    l1 += __shfl_xor_sync(0xFFFFFFFFu, l1, 1);
    l1 += __shfl_xor_sync(0xFFFFFFFFu, l1, 2);
    const float inv0 = 1.0f / l0, inv1 = 1.0f / l1;

    const int token0 = b * NN + q0;
    const size_t tbase = (size_t)(token0 >> 7) * NCHUNK;
    const int row0 = token0 & 127;
#pragma unroll
    for (int nb = 0; nb < 6; nb++) {
        int d = nb * 8 + (lane & 3) * 2;
        int c = h * HD + d;
        int c6 = c >> 6;
        unsigned colc = (unsigned)(c & 63);
#pragma unroll
        for (int half = 0; half < 2; half++) {
            int row = row0 + half * 8;
            float vx = (half == 0 ? Oacc[nb][0] * inv0 : Oacc[nb][2] * inv1);
            float vy = (half == 0 ? Oacc[nb][1] * inv0 : Oacc[nb][3] * inv1);
            uint32_t hp = packbf2(vx, vy);
            uint32_t lp = packbf2(vx - lo_as_f(hp), vy - hi_as_f(hp));
            unsigned off = (unsigned)(row * 128) +
                           (((colc >> 3) ^ (row & 7)) << 4) + (colc & 7) * 2;
            *(uint32_t*)((char*)(g_AT + (tbase + c6) * 8192) + off) = hp;
            *(uint32_t*)((char*)(g_AT + (tbase + 6 + c6) * 8192) + off) = hp;
            *(uint32_t*)((char*)(g_AT + (tbase + 12 + c6) * 8192) + off) = lp;
        }
    }
}

// ---------------------------------------------------------------------------
extern "C" void kernel_launch(void* const* d_in, const int* in_sizes, int n_in,
                              void* d_out, int out_size) {
    const float* x      = (const float*)d_in[0];
    const float* qkv_w  = (const float*)d_in[1];
    const float* qkv_b  = (const float*)d_in[2];
    const float* proj_w = (const float*)d_in[3];
    const float* proj_b = (const float*)d_in[4];
    const float* mlp_w1 = (const float*)d_in[5];
    const float* mlp_b1 = (const float*)d_in[6];
    const float* mlp_w2 = (const float*)d_in[7];
    const float* mlp_b2 = (const float*)d_in[8];
    float* out = (float*)d_out;

    cudaFuncSetAttribute(attn_mma, cudaFuncAttributeMaxDynamicSharedMemorySize, ATTN_SMEM);

    bias_kernel<<<(NBIAS + 255) / 256, 256>>>(mlp_w1, mlp_b1, mlp_w2, mlp_b2);
    conv_all<<<NCHUNK * (MT_QKV + NT_QKV + MT_PROJ), 256>>>(x, qkv_w, proj_w);
    gemm_qkv_mma<<<dim3(NT_QKV, MT_QKV), 256>>>(qkv_b);
    attn_mma<<<dim3(8, NH, BB), 256, ATTN_SMEM>>>();
    gemm_proj_mma<<<dim3(NT_PROJ, MT_PROJ), 256>>>(proj_b, out);
}